// round 14
// baseline (speedup 1.0000x reference)
#include <cuda_runtime.h>
#include <cuda_fp16.h>
#include <math.h>
#include <stdint.h>

#define SL   2048
#define DM   512
#define DI   1024
#define DS   16
#define DXZ  2048   // 2*DI
#define NSP  1056   // DI + 2*DS
#define NSP_PAD 1152
#define NCH  16
#define CL   128    // SL / NCH

// ---------------- fp32 scratch ----------------
__device__ float g_xz[2 * SL * DXZ];      // in-proj output: x_ssm | z
__device__ float g_xconv[2 * SL * DI];    // post depthwise conv (pre-silu)
__device__ float g_sp[2 * SL * NSP];      // xp-proj output: delta | B | C
__device__ float g_dt[2 * SL * DI];       // softplus(delta @ dtW + dtb)
// scan chunk scratch, [b][ch][d] layouts for coalescing
__device__ float g_dtsum[2 * NCH * DI];
__device__ float g_hpart[2 * NCH * DI * DS];

// ---------------- fp16 activations (A operands) ----------------
__device__ __align__(16) __half g_X2h[2 * SL * DM];
__device__ __align__(16) __half g_sxh[2 * SL * DI];
__device__ __align__(16) __half g_dh [2 * SL * DI];
__device__ __align__(16) __half g_yzh[2 * SL * DI];
__device__ __align__(16) __half g_cth[SL * 2 * DM];
// ---------------- fp16 transposed weights [Npad][K] ----------------
__device__ __align__(16) __half g_inW [2 * DXZ * DM];
__device__ __align__(16) __half g_xpW [2 * NSP_PAD * DI];
__device__ __align__(16) __half g_dtW [2 * DI * DI];
__device__ __align__(16) __half g_outW[2 * DM * DI];
__device__ __align__(16) __half g_fuW [DM * 2 * DM];

// ---------------- helpers ----------------
__device__ __forceinline__ float siluf(float v) { return v / (1.0f + __expf(-v)); }

__device__ __forceinline__ uint32_t smem_u32(const void* p) {
    uint32_t a;
    asm("{ .reg .u64 t; cvta.to.shared.u64 t, %1; cvt.u32.u64 %0, t; }" : "=r"(a) : "l"(p));
    return a;
}
__device__ __forceinline__ void cp16(uint32_t dst, const void* src) {
    asm volatile("cp.async.cg.shared.global [%0], [%1], 16;" :: "r"(dst), "l"(src));
}
__device__ __forceinline__ void cp_commit() {
    asm volatile("cp.async.commit_group;" ::: "memory");
}
__device__ __forceinline__ void cp_wait1() {
    asm volatile("cp.async.wait_group 1;" ::: "memory");
}

#define LDSM_X4(r0, r1, r2, r3, addr) \
    asm volatile("ldmatrix.sync.aligned.m8n8.x4.shared.b16 {%0,%1,%2,%3}, [%4];" \
                 : "=r"(r0), "=r"(r1), "=r"(r2), "=r"(r3) : "r"(addr))

#define MMA16816(d, a, b) \
    asm volatile("mma.sync.aligned.m16n8k16.row.col.f32.f16.f16.f32 " \
                 "{%0,%1,%2,%3}, {%4,%5,%6,%7}, {%8,%9}, {%0,%1,%2,%3};" \
                 : "+f"((d)[0]), "+f"((d)[1]), "+f"((d)[2]), "+f"((d)[3]) \
                 : "r"((a)[0]), "r"((a)[1]), "r"((a)[2]), "r"((a)[3]), \
                   "r"((b)[0]), "r"((b)[1]))

#define SWZ(o) ((o) ^ (((o) >> 3) & 0x70))

// ---------------- prepare: x -> fwd + reversed bwd fp16 ----------------
__global__ void k_prepare(const float* __restrict__ x) {
    int idx = blockIdx.x * blockDim.x + threadIdx.x;
    if (idx < SL * DM) {
        int l = idx / DM, d = idx % DM;
        __half h = __float2half(x[idx]);
        g_X2h[idx] = h;
        g_X2h[(size_t)SL * DM + (size_t)(SL - 1 - l) * DM + d] = h;
    }
}

// ---------------- causal depthwise conv (K=4), x4-vectorized over channels ----------------
__global__ void k_conv(const float* __restrict__ fcw, const float* __restrict__ fcb,
                       const float* __restrict__ bcw, const float* __restrict__ bcb) {
    const int DQ = DI / 4;
    int idx = blockIdx.x * blockDim.x + threadIdx.x;
    if (idx >= 2 * SL * DQ) return;
    int b = idx / (SL * DQ);
    int r = idx - b * (SL * DQ);
    int l = r / DQ, dq = r - l * DQ;
    int d = dq * 4;
    const float* cw = b ? bcw : fcw;
    const float* cb = b ? bcb : fcb;
    const float* xs = g_xz + (size_t)b * SL * DXZ;

    float4 w0 = *(const float4*)(cw + (d + 0) * 4);
    float4 w1 = *(const float4*)(cw + (d + 1) * 4);
    float4 w2 = *(const float4*)(cw + (d + 2) * 4);
    float4 w3 = *(const float4*)(cw + (d + 3) * 4);
    const float* w0p = &w0.x;
    const float* w1p = &w1.x;
    const float* w2p = &w2.x;
    const float* w3p = &w3.x;
    float4 acc = *(const float4*)(cb + d);
#pragma unroll
    for (int k = 0; k < 4; k++) {
        int ls = l + k - 3;
        if (ls >= 0) {
            float4 xv = *(const float4*)(xs + (size_t)ls * DXZ + d);
            acc.x += w0p[k] * xv.x;
            acc.y += w1p[k] * xv.y;
            acc.z += w2p[k] * xv.z;
            acc.w += w3p[k] * xv.w;
        }
    }
    size_t gbase = (size_t)b * SL * DI + (size_t)l * DI + d;
    *(float4*)(g_xconv + gbase) = acc;
    __half2* sx = (__half2*)(g_sxh + gbase);
    sx[0] = __floats2half2_rn(siluf(acc.x), siluf(acc.y));
    sx[1] = __floats2half2_rn(siluf(acc.z), siluf(acc.w));
}

// ---------------- fused weight transpose to fp16 (all 9 weights, 1 launch) ----------------
struct WtJobs {
    const float* W[9];
    __half* Bt[9];
    int K[9], N[9], bx[9];
    int ofs[10];
};

__global__ void k_wt_all(WtJobs jw) {
    __shared__ float s[32][33];
    int bxg = blockIdx.x;
    int j = 0;
#pragma unroll
    for (int q = 0; q < 9; q++) if (bxg >= jw.ofs[q + 1]) j = q + 1;
    int local = bxg - jw.ofs[j];
    int K = jw.K[j], N = jw.N[j], bxn = jw.bx[j];
    int nb = (local % bxn) * 32, kb = (local / bxn) * 32;
    const float* __restrict__ W = jw.W[j];
    __half* __restrict__ Bt = jw.Bt[j];
    int tx = threadIdx.x, ty = threadIdx.y;
#pragma unroll
    for (int q = 0; q < 32; q += 8) {
        int k = kb + ty + q, n = nb + tx;
        s[ty + q][tx] = (n < N) ? W[(size_t)k * N + n] : 0.0f;
    }
    __syncthreads();
#pragma unroll
    for (int q = 0; q < 32; q += 8) {
        int n = nb + ty + q, k = kb + tx;
        Bt[(size_t)n * K + k] = __float2half(s[tx][ty + q]);
    }
}

// ---------------- fp16 1-term GEMM: C = A @ W^T + bias ----------------
// Template BM: CTA tile BM x 128, K-slab 64, 8 warps, 2-stage cp.async pipeline.
struct TArgs {
    const __half *Ah[2], *Bh[2];
    const float* bias[2];
    float* C[2];
    __half* Dh[2];
    int M, N, K, ldc, ldd, dlim;
    int rev[2];
};

#define BTILE_B 16384      // 128 x 64 fp16

// EPI: 0 none, 1 softplus.  MODE: 0 fp32 C, 1 fp32 C + fp16 D (cols<dlim), 2 fp16 D only.
template <int EPI, int MODE, int BM>
__global__ void __launch_bounds__(256, 1) k_mma_gemm(TArgs ga) {
    constexpr int MI = BM / 64;              // m microtiles per warp (1, 2 or 4)
    constexpr int TILE_A = BM * 128;
    constexpr int STG = TILE_A + BTILE_B;
    extern __shared__ __align__(1024) char smem[];
    const int bz = blockIdx.z;
    const __half* __restrict__ Ah = ga.Ah[bz];
    const __half* __restrict__ Bh = ga.Bh[bz];
    const float* __restrict__ bias = ga.bias[bz];
    float* __restrict__ C = ga.C[bz];
    __half* __restrict__ D = ga.Dh[bz];
    const int K = ga.K, N = ga.N, ldc = ga.ldc, ldd = ga.ldd, rev = ga.rev[bz];
    const int m0 = blockIdx.y * BM, n0 = blockIdx.x * 128;

    const int tid = threadIdx.x, wid = tid >> 5, lane = tid & 31;
    const int wm = (wid & 3) * (16 * MI);
    const int wn = (wid >> 2) * 64;
    const uint32_t sb = smem_u32(smem);

    float acc[MI][8][4];
#pragma unroll
    for (int i = 0; i < MI; i++)
#pragma unroll
        for (int j = 0; j < 8; j++)
#pragma unroll
            for (int q = 0; q < 4; q++) acc[i][j][q] = 0.0f;

    const int nslab = K / 64;
    const __half* Abase = Ah + (size_t)m0 * K;
    const __half* Bbase = Bh + (size_t)n0 * K;

    auto load_slab = [&](uint32_t sdst, int kslab) {
        const int kof = kslab * 64;
#pragma unroll
        for (int i = 0; i < BM / 32; i++) {
            int idx = tid + i * 256;
            int r = idx >> 3, c = idx & 7;
            cp16(sdst + SWZ(r * 128 + c * 16), Abase + (size_t)r * K + kof + c * 8);
        }
#pragma unroll
        for (int i = 0; i < 4; i++) {
            int idx = tid + i * 256;
            int r = idx >> 3, c = idx & 7;
            cp16(sdst + TILE_A + SWZ(r * 128 + c * 16), Bbase + (size_t)r * K + kof + c * 8);
        }
    };

    load_slab(sb, 0);
    cp_commit();
    if (nslab > 1) load_slab(sb + STG, 1);
    cp_commit();

    const int a_row = (lane & 15);
    const int a_kc  = (lane >> 4) * 16;
    const int b_row = (lane & 7) + ((lane >> 4) << 3);
    const int b_kc  = ((lane >> 3) & 1) * 16;

    for (int sl = 0; sl < nslab; sl++) {
        cp_wait1();
        __syncthreads();
        const uint32_t st = sb + (sl & 1) * STG;
        const uint32_t stA = st, stB = st + TILE_A;

#pragma unroll
        for (int ks = 0; ks < 4; ks++) {
            uint32_t ah[MI][4];
#pragma unroll
            for (int mi = 0; mi < MI; mi++) {
                uint32_t off = SWZ((wm + mi * 16 + a_row) * 128 + ks * 32 + a_kc);
                LDSM_X4(ah[mi][0], ah[mi][1], ah[mi][2], ah[mi][3], stA + off);
            }
            uint32_t bh[8][2];
#pragma unroll
            for (int jj = 0; jj < 4; jj++) {
                uint32_t off = SWZ((wn + jj * 16 + b_row) * 128 + ks * 32 + b_kc);
                uint32_t r0, r1, r2, r3;
                LDSM_X4(r0, r1, r2, r3, stB + off);
                bh[jj * 2][0] = r0; bh[jj * 2][1] = r1;
                bh[jj * 2 + 1][0] = r2; bh[jj * 2 + 1][1] = r3;
            }
#pragma unroll
            for (int mi = 0; mi < MI; mi++)
#pragma unroll
                for (int nj = 0; nj < 8; nj++)
                    MMA16816(acc[mi][nj], ah[mi], bh[nj]);
        }
        __syncthreads();
        if (sl + 2 < nslab) load_slab(sb + (sl & 1) * STG, sl + 2);
        cp_commit();
    }

    // epilogue
    const int gid = lane >> 2, tig = lane & 3;
#pragma unroll
    for (int mi = 0; mi < MI; mi++) {
        int mb = m0 + wm + mi * 16 + gid;
        int r1 = rev ? (ga.M - 1 - mb) : mb;
        int r2 = rev ? (ga.M - 1 - (mb + 8)) : (mb + 8);
#pragma unroll
        for (int nj = 0; nj < 8; nj++) {
            int nc = n0 + wn + nj * 8 + tig * 2;
            if (nc < N) {
                float b0 = bias[nc], b1 = bias[nc + 1];
                float v0 = acc[mi][nj][0] + b0;
                float v1 = acc[mi][nj][1] + b1;
                float v2 = acc[mi][nj][2] + b0;
                float v3 = acc[mi][nj][3] + b1;
                if (EPI == 1) {
                    v0 = (v0 > 20.0f) ? v0 : log1pf(__expf(v0));
                    v1 = (v1 > 20.0f) ? v1 : log1pf(__expf(v1));
                    v2 = (v2 > 20.0f) ? v2 : log1pf(__expf(v2));
                    v3 = (v3 > 20.0f) ? v3 : log1pf(__expf(v3));
                }
                if (MODE == 0 || MODE == 1) {
                    *(float2*)&C[(size_t)r1 * ldc + nc] = make_float2(v0, v1);
                    *(float2*)&C[(size_t)r2 * ldc + nc] = make_float2(v2, v3);
                }
                if ((MODE == 1 && nc < ga.dlim) || MODE == 2) {
                    *(__half2*)&D[(size_t)r1 * ldd + nc] = __floats2half2_rn(v0, v1);
                    *(__half2*)&D[(size_t)r2 * ldd + nc] = __floats2half2_rn(v2, v3);
                }
            }
        }
    }
}

#define SMEM64  (2 * (64 * 128 + BTILE_B))    // 49152
#define SMEM128 (2 * (128 * 128 + BTILE_B))   // 65536
#define SMEM256 (2 * (256 * 128 + BTILE_B))   // 98304

// ---------------- chunked selective scan ----------------
// phase A: per (dir, d, chunk) local recurrence from h=0; [b][ch][d][s] coalesced stores
__global__ void k_scanA(const float* __restrict__ A_log) {
    __shared__ float sB[CL][DS];
    const int b = blockIdx.z, ch = blockIdx.y;
    const int d = blockIdx.x * 128 + threadIdx.x;
    const float* __restrict__ spp = g_sp + (size_t)b * SL * NSP;
    for (int i = threadIdx.x; i < CL * DS; i += 128) {
        int l = i >> 4, s = i & 15;
        sB[l][s] = spp[(size_t)(ch * CL + l) * NSP + DI + s];
    }
    __syncthreads();
    float Ac[DS];
#pragma unroll
    for (int s = 0; s < DS; s++) Ac[s] = -__expf(A_log[d * DS + s]);
    float h[DS];
#pragma unroll
    for (int s = 0; s < DS; s++) h[s] = 0.0f;
    float dts = 0.0f;
    const float* __restrict__ dtp = g_dt + (size_t)b * SL * DI;
    const float* __restrict__ xcp = g_xconv + (size_t)b * SL * DI;
    for (int l = 0; l < CL; l++) {
        int gl = ch * CL + l;
        float dt = dtp[(size_t)gl * DI + d];
        float xv = xcp[(size_t)gl * DI + d];
        dts += dt;
        float du = dt * xv;
#pragma unroll
        for (int s = 0; s < DS; s++) h[s] = __expf(dt * Ac[s]) * h[s] + du * sB[l][s];
    }
    size_t base = ((size_t)(b * NCH + ch) * DI + d) * DS;
#pragma unroll
    for (int s = 0; s < DS; s++) g_hpart[base + s] = h[s];
    g_dtsum[(size_t)(b * NCH + ch) * DI + d] = dts;
}

// phase C: inline chunk-combine (former scanB) + replay + gated fp16 output
__global__ void k_scanC(const float* __restrict__ A_log, const float* __restrict__ Dp) {
    __shared__ float sB[CL][DS];
    __shared__ float sC[CL][DS];
    const int b = blockIdx.z, ch = blockIdx.y;
    const int d = blockIdx.x * 128 + threadIdx.x;
    const float* __restrict__ spp = g_sp + (size_t)b * SL * NSP;
    for (int i = threadIdx.x; i < CL * DS; i += 128) {
        int l = i >> 4, s = i & 15;
        sB[l][s] = spp[(size_t)(ch * CL + l) * NSP + DI + s];
        sC[l][s] = spp[(size_t)(ch * CL + l) * NSP + DI + DS + s];
    }
    __syncthreads();
    float Ac[DS];
#pragma unroll
    for (int s = 0; s < DS; s++) Ac[s] = -__expf(A_log[d * DS + s]);

    // combine chunks 0..ch-1 to get h_init for this chunk
    float h[DS];
#pragma unroll
    for (int s = 0; s < DS; s++) h[s] = 0.0f;
    for (int cc = 0; cc < ch; cc++) {
        float dsum = g_dtsum[(size_t)(b * NCH + cc) * DI + d];
        size_t hb = ((size_t)(b * NCH + cc) * DI + d) * DS;
#pragma unroll
        for (int s = 0; s < DS; s++)
            h[s] = __expf(dsum * Ac[s]) * h[s] + g_hpart[hb + s];
    }

    const float Dv = Dp[d];
    const float* __restrict__ dtp = g_dt + (size_t)b * SL * DI;
    const float* __restrict__ xcp = g_xconv + (size_t)b * SL * DI;
    const float* __restrict__ zp  = g_xz + (size_t)b * SL * DXZ + DI;
    __half* __restrict__ yh = g_yzh + (size_t)b * SL * DI;
    for (int l = 0; l < CL; l++) {
        int gl = ch * CL + l;
        float dt = dtp[(size_t)gl * DI + d];
        float xv = xcp[(size_t)gl * DI + d];
        float du = dt * xv;
        float y = Dv * xv;
#pragma unroll
        for (int s = 0; s < DS; s++) {
            h[s] = __expf(dt * Ac[s]) * h[s] + du * sB[l][s];
            y += h[s] * sC[l][s];
        }
        float zv = zp[(size_t)gl * DXZ + d];
        yh[(size_t)gl * DI + d] = __float2half(y * siluf(zv));
    }
}

// ---------------- host orchestration ----------------
extern "C" void kernel_launch(void* const* d_in, const int* in_sizes, int n_in,
                              void* d_out, int out_size) {
    const float* x = (const float*)d_in[0];
    const float* inW[2]  = {(const float*)d_in[1],  (const float*)d_in[11]};
    const float* inb[2]  = {(const float*)d_in[2],  (const float*)d_in[12]};
    const float* cw[2]   = {(const float*)d_in[3],  (const float*)d_in[13]};
    const float* cb[2]   = {(const float*)d_in[4],  (const float*)d_in[14]};
    const float* xpW[2]  = {(const float*)d_in[5],  (const float*)d_in[15]};
    const float* xpb[2]  = {(const float*)d_in[6],  (const float*)d_in[16]};
    const float* dtW[2]  = {(const float*)d_in[7],  (const float*)d_in[17]};
    const float* dtb[2]  = {(const float*)d_in[8],  (const float*)d_in[18]};
    const float* outW[2] = {(const float*)d_in[9],  (const float*)d_in[19]};
    const float* outb[2] = {(const float*)d_in[10], (const float*)d_in[20]};
    const float* A_log   = (const float*)d_in[21];
    const float* Dp      = (const float*)d_in[22];
    const float* fuW     = (const float*)d_in[23];
    const float* fub     = (const float*)d_in[24];
    float* out = (float*)d_out;

    cudaFuncSetAttribute(k_mma_gemm<0,0,256>, cudaFuncAttributeMaxDynamicSharedMemorySize, SMEM256);
    cudaFuncSetAttribute(k_mma_gemm<0,1,256>, cudaFuncAttributeMaxDynamicSharedMemorySize, SMEM256);
    cudaFuncSetAttribute(k_mma_gemm<1,0,256>, cudaFuncAttributeMaxDynamicSharedMemorySize, SMEM256);
    cudaFuncSetAttribute(k_mma_gemm<0,2,128>, cudaFuncAttributeMaxDynamicSharedMemorySize, SMEM128);
    cudaFuncSetAttribute(k_mma_gemm<0,0,64>,  cudaFuncAttributeMaxDynamicSharedMemorySize, SMEM64);

    float *xz, *sp, *dtbuf;
    __half *X2h, *sxh, *dh, *yzh, *cth;
    __half *inWt, *xpWt, *dtWt, *outWt, *fuWt;
    cudaGetSymbolAddress((void**)&xz, g_xz);
    cudaGetSymbolAddress((void**)&sp, g_sp);
    cudaGetSymbolAddress((void**)&dtbuf, g_dt);
    cudaGetSymbolAddress((void**)&X2h, g_X2h);
    cudaGetSymbolAddress((void**)&sxh, g_sxh);
    cudaGetSymbolAddress((void**)&dh, g_dh);
    cudaGetSymbolAddress((void**)&yzh, g_yzh);
    cudaGetSymbolAddress((void**)&cth, g_cth);
    cudaGetSymbolAddress((void**)&inWt, g_inW);
    cudaGetSymbolAddress((void**)&xpWt, g_xpW);
    cudaGetSymbolAddress((void**)&dtWt, g_dtW);
    cudaGetSymbolAddress((void**)&outWt, g_outW);
    cudaGetSymbolAddress((void**)&fuWt, g_fuW);

    // 0. fused weight transpose (9 jobs, 1 launch)
    {
        WtJobs jw;
        const float* Ws[9] = {inW[0], inW[1], xpW[0], xpW[1], dtW[0], dtW[1], outW[0], outW[1], fuW};
        __half* Ts[9] = {inWt, inWt + (size_t)DXZ * DM, xpWt, xpWt + (size_t)NSP_PAD * DI,
                         dtWt, dtWt + (size_t)DI * DI, outWt, outWt + (size_t)DM * DI, fuWt};
        int Ks[9]  = {DM, DM, DI, DI, DI, DI, DI, DI, 2 * DM};
        int Ns[9]  = {DXZ, DXZ, NSP, NSP, DI, DI, DM, DM, DM};
        int Nps[9] = {DXZ, DXZ, NSP_PAD, NSP_PAD, DI, DI, DM, DM, DM};
        int ofs = 0;
        jw.ofs[0] = 0;
        for (int j = 0; j < 9; j++) {
            jw.W[j] = Ws[j]; jw.Bt[j] = Ts[j];
            jw.K[j] = Ks[j]; jw.N[j] = Ns[j]; jw.bx[j] = Nps[j] / 32;
            ofs += (Nps[j] / 32) * (Ks[j] / 32);
            jw.ofs[j + 1] = ofs;
        }
        k_wt_all<<<ofs, dim3(32, 8)>>>(jw);
    }

    // 1. prepare inputs
    k_prepare<<<(SL * DM + 255) / 256, 256>>>(x);

    // 2. in-projection: [2048 x 2048], K=512  (BM=256)
    {
        TArgs ga = {};
        for (int b = 0; b < 2; b++) {
            ga.Ah[b] = X2h + (size_t)b * SL * DM;
            ga.Bh[b] = inWt + (size_t)b * DXZ * DM;
            ga.bias[b] = inb[b];
            ga.C[b] = xz + (size_t)b * SL * DXZ;
            ga.rev[b] = 0;
        }
        ga.M = SL; ga.N = DXZ; ga.K = DM; ga.ldc = DXZ;
        k_mma_gemm<0,0,256><<<dim3(DXZ / 128, SL / 256, 2), 256, SMEM256>>>(ga);
    }

    // 3. depthwise conv + silu (fp16 out), x4 vectorized
    k_conv<<<(2 * SL * (DI / 4) + 255) / 256, 256>>>(cw[0], cb[0], cw[1], cb[1]);

    // 4. xp-projection: fp32 sp + fused fp16 delta split  (BM=256)
    {
        TArgs ga = {};
        for (int b = 0; b < 2; b++) {
            ga.Ah[b] = sxh + (size_t)b * SL * DI;
            ga.Bh[b] = xpWt + (size_t)b * NSP_PAD * DI;
            ga.bias[b] = xpb[b];
            ga.C[b] = sp + (size_t)b * SL * NSP;
            ga.Dh[b] = dh + (size_t)b * SL * DI;
            ga.rev[b] = 0;
        }
        ga.M = SL; ga.N = NSP; ga.K = DI; ga.ldc = NSP; ga.ldd = DI; ga.dlim = DI;
        k_mma_gemm<0,1,256><<<dim3(NSP_PAD / 128, SL / 256, 2), 256, SMEM256>>>(ga);
    }

    // 5. dt-projection + softplus: [2048 x 1024], K=1024  (BM=256)
    {
        TArgs ga = {};
        for (int b = 0; b < 2; b++) {
            ga.Ah[b] = dh + (size_t)b * SL * DI;
            ga.Bh[b] = dtWt + (size_t)b * DI * DI;
            ga.bias[b] = dtb[b];
            ga.C[b] = dtbuf + (size_t)b * SL * DI;
            ga.rev[b] = 0;
        }
        ga.M = SL; ga.N = DI; ga.K = DI; ga.ldc = DI;
        k_mma_gemm<1,0,256><<<dim3(DI / 128, SL / 256, 2), 256, SMEM256>>>(ga);
    }

    // 6. chunked selective scan (A, then C with inlined combine)
    k_scanA<<<dim3(DI / 128, NCH, 2), 128>>>(A_log);
    k_scanC<<<dim3(DI / 128, NCH, 2), 128>>>(A_log, Dp);

    // 7. out-projection: fp16 concat only (bwd rows reversed back)  (BM=128)
    {
        TArgs ga = {};
        for (int b = 0; b < 2; b++) {
            ga.Ah[b] = yzh + (size_t)b * SL * DI;
            ga.Bh[b] = outWt + (size_t)b * DM * DI;
            ga.bias[b] = outb[b];
            ga.Dh[b] = cth + b * DM;
            ga.rev[b] = (b == 1);
        }
        ga.M = SL; ga.N = DM; ga.K = DI; ga.ldd = 2 * DM;
        k_mma_gemm<0,2,128><<<dim3(DM / 128, SL / 128, 2), 256, SMEM128>>>(ga);
    }

    // 8. fusion: [2048 x 512], K=1024  (BM=64 -> 128 CTAs, full chip)
    {
        TArgs ga = {};
        ga.Ah[0] = ga.Ah[1] = cth;
        ga.Bh[0] = ga.Bh[1] = fuWt;
        ga.bias[0] = ga.bias[1] = fub;
        ga.C[0] = ga.C[1] = out;
        ga.rev[0] = ga.rev[1] = 0;
        ga.M = SL; ga.N = DM; ga.K = 2 * DM; ga.ldc = DM;
        k_mma_gemm<0,0,64><<<dim3(DM / 128, SL / 64, 1), 256, SMEM64>>>(ga);
    }
}

// round 15
// speedup vs baseline: 1.0708x; 1.0708x over previous
#include <cuda_runtime.h>
#include <cuda_fp16.h>
#include <math.h>
#include <stdint.h>

#define SL   2048
#define DM   512
#define DI   1024
#define DS   16
#define DXZ  2048   // 2*DI
#define NSP  1056   // DI + 2*DS
#define NSP_PAD 1152
#define NCH  16
#define CL   128    // SL / NCH

// ---------------- fp32 scratch ----------------
__device__ float g_xz[2 * SL * DXZ];      // in-proj output: x_ssm | z
__device__ float g_xconv[2 * SL * DI];    // post depthwise conv (pre-silu)
__device__ float g_sp[2 * SL * NSP];      // xp-proj output: delta | B | C
__device__ float g_dt[2 * SL * DI];       // softplus(delta @ dtW + dtb)
// scan chunk scratch, [b][ch][d] layouts for coalescing
__device__ float g_dtsum[2 * NCH * DI];
__device__ float g_hpart[2 * NCH * DI * DS];

// ---------------- fp16 activations (A operands) ----------------
__device__ __align__(16) __half g_X2h[2 * SL * DM];
__device__ __align__(16) __half g_sxh[2 * SL * DI];
__device__ __align__(16) __half g_dh [2 * SL * DI];
__device__ __align__(16) __half g_yzh[2 * SL * DI];
__device__ __align__(16) __half g_cth[SL * 2 * DM];
// ---------------- fp16 transposed weights [Npad][K] ----------------
__device__ __align__(16) __half g_inW [2 * DXZ * DM];
__device__ __align__(16) __half g_xpW [2 * NSP_PAD * DI];
__device__ __align__(16) __half g_dtW [2 * DI * DI];
__device__ __align__(16) __half g_outW[2 * DM * DI];
__device__ __align__(16) __half g_fuW [DM * 2 * DM];

// ---------------- helpers ----------------
__device__ __forceinline__ float siluf(float v) { return v / (1.0f + __expf(-v)); }

__device__ __forceinline__ uint32_t smem_u32(const void* p) {
    uint32_t a;
    asm("{ .reg .u64 t; cvta.to.shared.u64 t, %1; cvt.u32.u64 %0, t; }" : "=r"(a) : "l"(p));
    return a;
}
__device__ __forceinline__ void cp16(uint32_t dst, const void* src) {
    asm volatile("cp.async.cg.shared.global [%0], [%1], 16;" :: "r"(dst), "l"(src));
}
__device__ __forceinline__ void cp_commit() {
    asm volatile("cp.async.commit_group;" ::: "memory");
}
__device__ __forceinline__ void cp_wait1() {
    asm volatile("cp.async.wait_group 1;" ::: "memory");
}

#define LDSM_X4(r0, r1, r2, r3, addr) \
    asm volatile("ldmatrix.sync.aligned.m8n8.x4.shared.b16 {%0,%1,%2,%3}, [%4];" \
                 : "=r"(r0), "=r"(r1), "=r"(r2), "=r"(r3) : "r"(addr))

#define MMA16816(d, a, b) \
    asm volatile("mma.sync.aligned.m16n8k16.row.col.f32.f16.f16.f32 " \
                 "{%0,%1,%2,%3}, {%4,%5,%6,%7}, {%8,%9}, {%0,%1,%2,%3};" \
                 : "+f"((d)[0]), "+f"((d)[1]), "+f"((d)[2]), "+f"((d)[3]) \
                 : "r"((a)[0]), "r"((a)[1]), "r"((a)[2]), "r"((a)[3]), \
                   "r"((b)[0]), "r"((b)[1]))

#define SWZ(o) ((o) ^ (((o) >> 3) & 0x70))

// ---------------- prepare: x -> fwd + reversed bwd fp16 ----------------
__global__ void k_prepare(const float* __restrict__ x) {
    int idx = blockIdx.x * blockDim.x + threadIdx.x;
    if (idx < SL * DM) {
        int l = idx / DM, d = idx % DM;
        __half h = __float2half(x[idx]);
        g_X2h[idx] = h;
        g_X2h[(size_t)SL * DM + (size_t)(SL - 1 - l) * DM + d] = h;
    }
}

// ---------------- causal depthwise conv (K=4) — proven R11 scalar form ----------------
__global__ void k_conv(const float* __restrict__ fcw, const float* __restrict__ fcb,
                       const float* __restrict__ bcw, const float* __restrict__ bcb) {
    int idx = blockIdx.x * blockDim.x + threadIdx.x;
    if (idx >= 2 * SL * DI) return;
    int b = idx / (SL * DI);
    int r = idx - b * SL * DI;
    int l = r / DI, d = r % DI;
    const float* cw = b ? bcw : fcw;
    const float* cb = b ? bcb : fcb;
    const float* xs = g_xz + (size_t)b * SL * DXZ;
    float acc = cb[d];
#pragma unroll
    for (int k = 0; k < 4; k++) {
        int ls = l + k - 3;
        if (ls >= 0) acc += cw[d * 4 + k] * xs[(size_t)ls * DXZ + d];
    }
    g_xconv[idx] = acc;
    g_sxh[idx] = __float2half(siluf(acc));
}

// ---------------- fused weight transpose to fp16 (all 9 weights, 1 launch) ----------------
struct WtJobs {
    const float* W[9];
    __half* Bt[9];
    int K[9], N[9], bx[9];
    int ofs[10];
};

__global__ void k_wt_all(WtJobs jw) {
    __shared__ float s[32][33];
    int bxg = blockIdx.x;
    int j = 0;
#pragma unroll
    for (int q = 0; q < 9; q++) if (bxg >= jw.ofs[q + 1]) j = q + 1;
    int local = bxg - jw.ofs[j];
    int K = jw.K[j], N = jw.N[j], bxn = jw.bx[j];
    int nb = (local % bxn) * 32, kb = (local / bxn) * 32;
    const float* __restrict__ W = jw.W[j];
    __half* __restrict__ Bt = jw.Bt[j];
    int tx = threadIdx.x, ty = threadIdx.y;
#pragma unroll
    for (int q = 0; q < 32; q += 8) {
        int k = kb + ty + q, n = nb + tx;
        s[ty + q][tx] = (n < N) ? W[(size_t)k * N + n] : 0.0f;
    }
    __syncthreads();
#pragma unroll
    for (int q = 0; q < 32; q += 8) {
        int n = nb + ty + q, k = kb + tx;
        Bt[(size_t)n * K + k] = __float2half(s[tx][ty + q]);
    }
}

// ---------------- fp16 1-term GEMM: C = A @ W^T + bias ----------------
// CTA tile BM x 128, K-slab 64, 8 warps, 2-stage cp.async pipeline, 2 CTAs/SM.
struct TArgs {
    const __half *Ah[2], *Bh[2];
    const float* bias[2];
    float* C[2];
    __half* Dh[2];
    int M, N, K, ldc, ldd, dlim;
    int rev[2];
};

#define BTILE_B 16384      // 128 x 64 fp16

// EPI: 0 none, 1 softplus.  MODE: 0 fp32 C, 1 fp32 C + fp16 D (cols<dlim), 2 fp16 D only.
template <int EPI, int MODE, int BM>
__global__ void __launch_bounds__(256, 2) k_mma_gemm(TArgs ga) {
    constexpr int MI = BM / 64;              // m microtiles per warp (1 or 2)
    constexpr int TILE_A = BM * 128;
    constexpr int STG = TILE_A + BTILE_B;
    extern __shared__ __align__(1024) char smem[];
    const int bz = blockIdx.z;
    const __half* __restrict__ Ah = ga.Ah[bz];
    const __half* __restrict__ Bh = ga.Bh[bz];
    const float* __restrict__ bias = ga.bias[bz];
    float* __restrict__ C = ga.C[bz];
    __half* __restrict__ D = ga.Dh[bz];
    const int K = ga.K, N = ga.N, ldc = ga.ldc, ldd = ga.ldd, rev = ga.rev[bz];
    const int m0 = blockIdx.y * BM, n0 = blockIdx.x * 128;

    const int tid = threadIdx.x, wid = tid >> 5, lane = tid & 31;
    const int wm = (wid & 3) * (16 * MI);
    const int wn = (wid >> 2) * 64;
    const uint32_t sb = smem_u32(smem);

    float acc[MI][8][4];
#pragma unroll
    for (int i = 0; i < MI; i++)
#pragma unroll
        for (int j = 0; j < 8; j++)
#pragma unroll
            for (int q = 0; q < 4; q++) acc[i][j][q] = 0.0f;

    const int nslab = K / 64;
    const __half* Abase = Ah + (size_t)m0 * K;
    const __half* Bbase = Bh + (size_t)n0 * K;

    auto load_slab = [&](uint32_t sdst, int kslab) {
        const int kof = kslab * 64;
#pragma unroll
        for (int i = 0; i < BM / 32; i++) {
            int idx = tid + i * 256;
            int r = idx >> 3, c = idx & 7;
            cp16(sdst + SWZ(r * 128 + c * 16), Abase + (size_t)r * K + kof + c * 8);
        }
#pragma unroll
        for (int i = 0; i < 4; i++) {
            int idx = tid + i * 256;
            int r = idx >> 3, c = idx & 7;
            cp16(sdst + TILE_A + SWZ(r * 128 + c * 16), Bbase + (size_t)r * K + kof + c * 8);
        }
    };

    load_slab(sb, 0);
    cp_commit();
    if (nslab > 1) load_slab(sb + STG, 1);
    cp_commit();

    const int a_row = (lane & 15);
    const int a_kc  = (lane >> 4) * 16;
    const int b_row = (lane & 7) + ((lane >> 4) << 3);
    const int b_kc  = ((lane >> 3) & 1) * 16;

    for (int sl = 0; sl < nslab; sl++) {
        cp_wait1();
        __syncthreads();
        const uint32_t st = sb + (sl & 1) * STG;
        const uint32_t stA = st, stB = st + TILE_A;

#pragma unroll
        for (int ks = 0; ks < 4; ks++) {
            uint32_t ah[MI][4];
#pragma unroll
            for (int mi = 0; mi < MI; mi++) {
                uint32_t off = SWZ((wm + mi * 16 + a_row) * 128 + ks * 32 + a_kc);
                LDSM_X4(ah[mi][0], ah[mi][1], ah[mi][2], ah[mi][3], stA + off);
            }
            uint32_t bh[8][2];
#pragma unroll
            for (int jj = 0; jj < 4; jj++) {
                uint32_t off = SWZ((wn + jj * 16 + b_row) * 128 + ks * 32 + b_kc);
                uint32_t r0, r1, r2, r3;
                LDSM_X4(r0, r1, r2, r3, stB + off);
                bh[jj * 2][0] = r0; bh[jj * 2][1] = r1;
                bh[jj * 2 + 1][0] = r2; bh[jj * 2 + 1][1] = r3;
            }
#pragma unroll
            for (int mi = 0; mi < MI; mi++)
#pragma unroll
                for (int nj = 0; nj < 8; nj++)
                    MMA16816(acc[mi][nj], ah[mi], bh[nj]);
        }
        __syncthreads();
        if (sl + 2 < nslab) load_slab(sb + (sl & 1) * STG, sl + 2);
        cp_commit();
    }

    // epilogue
    const int gid = lane >> 2, tig = lane & 3;
#pragma unroll
    for (int mi = 0; mi < MI; mi++) {
        int mb = m0 + wm + mi * 16 + gid;
        int r1 = rev ? (ga.M - 1 - mb) : mb;
        int r2 = rev ? (ga.M - 1 - (mb + 8)) : (mb + 8);
#pragma unroll
        for (int nj = 0; nj < 8; nj++) {
            int nc = n0 + wn + nj * 8 + tig * 2;
            if (nc < N) {
                float b0 = bias[nc], b1 = bias[nc + 1];
                float v0 = acc[mi][nj][0] + b0;
                float v1 = acc[mi][nj][1] + b1;
                float v2 = acc[mi][nj][2] + b0;
                float v3 = acc[mi][nj][3] + b1;
                if (EPI == 1) {
                    v0 = (v0 > 20.0f) ? v0 : log1pf(__expf(v0));
                    v1 = (v1 > 20.0f) ? v1 : log1pf(__expf(v1));
                    v2 = (v2 > 20.0f) ? v2 : log1pf(__expf(v2));
                    v3 = (v3 > 20.0f) ? v3 : log1pf(__expf(v3));
                }
                if (MODE == 0 || MODE == 1) {
                    *(float2*)&C[(size_t)r1 * ldc + nc] = make_float2(v0, v1);
                    *(float2*)&C[(size_t)r2 * ldc + nc] = make_float2(v2, v3);
                }
                if ((MODE == 1 && nc < ga.dlim) || MODE == 2) {
                    *(__half2*)&D[(size_t)r1 * ldd + nc] = __floats2half2_rn(v0, v1);
                    *(__half2*)&D[(size_t)r2 * ldd + nc] = __floats2half2_rn(v2, v3);
                }
            }
        }
    }
}

#define SMEM64  (2 * (64 * 128 + BTILE_B))    // 49152
#define SMEM128 (2 * (128 * 128 + BTILE_B))   // 65536

// ---------------- chunked selective scan ----------------
// phase A: per (dir, d, chunk) local recurrence from h=0; [b][ch][d][s] coalesced stores
__global__ void k_scanA(const float* __restrict__ A_log) {
    __shared__ float sB[CL][DS];
    const int b = blockIdx.z, ch = blockIdx.y;
    const int d = blockIdx.x * 128 + threadIdx.x;
    const float* __restrict__ spp = g_sp + (size_t)b * SL * NSP;
    for (int i = threadIdx.x; i < CL * DS; i += 128) {
        int l = i >> 4, s = i & 15;
        sB[l][s] = spp[(size_t)(ch * CL + l) * NSP + DI + s];
    }
    __syncthreads();
    float Ac[DS];
#pragma unroll
    for (int s = 0; s < DS; s++) Ac[s] = -__expf(A_log[d * DS + s]);
    float h[DS];
#pragma unroll
    for (int s = 0; s < DS; s++) h[s] = 0.0f;
    float dts = 0.0f;
    const float* __restrict__ dtp = g_dt + (size_t)b * SL * DI;
    const float* __restrict__ xcp = g_xconv + (size_t)b * SL * DI;
    for (int l = 0; l < CL; l++) {
        int gl = ch * CL + l;
        float dt = dtp[(size_t)gl * DI + d];
        float xv = xcp[(size_t)gl * DI + d];
        dts += dt;
        float du = dt * xv;
#pragma unroll
        for (int s = 0; s < DS; s++) h[s] = __expf(dt * Ac[s]) * h[s] + du * sB[l][s];
    }
    size_t base = ((size_t)(b * NCH + ch) * DI + d) * DS;
#pragma unroll
    for (int s = 0; s < DS; s++) g_hpart[base + s] = h[s];
    g_dtsum[(size_t)(b * NCH + ch) * DI + d] = dts;
}

// phase C: inline chunk-combine + replay + gated fp16 output
__global__ void k_scanC(const float* __restrict__ A_log, const float* __restrict__ Dp) {
    __shared__ float sB[CL][DS];
    __shared__ float sC[CL][DS];
    const int b = blockIdx.z, ch = blockIdx.y;
    const int d = blockIdx.x * 128 + threadIdx.x;
    const float* __restrict__ spp = g_sp + (size_t)b * SL * NSP;
    for (int i = threadIdx.x; i < CL * DS; i += 128) {
        int l = i >> 4, s = i & 15;
        sB[l][s] = spp[(size_t)(ch * CL + l) * NSP + DI + s];
        sC[l][s] = spp[(size_t)(ch * CL + l) * NSP + DI + DS + s];
    }
    __syncthreads();
    float Ac[DS];
#pragma unroll
    for (int s = 0; s < DS; s++) Ac[s] = -__expf(A_log[d * DS + s]);

    // combine chunks 0..ch-1 to get h_init for this chunk
    float h[DS];
#pragma unroll
    for (int s = 0; s < DS; s++) h[s] = 0.0f;
    for (int cc = 0; cc < ch; cc++) {
        float dsum = g_dtsum[(size_t)(b * NCH + cc) * DI + d];
        size_t hb = ((size_t)(b * NCH + cc) * DI + d) * DS;
#pragma unroll
        for (int s = 0; s < DS; s++)
            h[s] = __expf(dsum * Ac[s]) * h[s] + g_hpart[hb + s];
    }

    const float Dv = Dp[d];
    const float* __restrict__ dtp = g_dt + (size_t)b * SL * DI;
    const float* __restrict__ xcp = g_xconv + (size_t)b * SL * DI;
    const float* __restrict__ zp  = g_xz + (size_t)b * SL * DXZ + DI;
    __half* __restrict__ yh = g_yzh + (size_t)b * SL * DI;
    for (int l = 0; l < CL; l++) {
        int gl = ch * CL + l;
        float dt = dtp[(size_t)gl * DI + d];
        float xv = xcp[(size_t)gl * DI + d];
        float du = dt * xv;
        float y = Dv * xv;
#pragma unroll
        for (int s = 0; s < DS; s++) {
            h[s] = __expf(dt * Ac[s]) * h[s] + du * sB[l][s];
            y += h[s] * sC[l][s];
        }
        float zv = zp[(size_t)gl * DXZ + d];
        yh[(size_t)gl * DI + d] = __float2half(y * siluf(zv));
    }
}

// ---------------- host orchestration ----------------
extern "C" void kernel_launch(void* const* d_in, const int* in_sizes, int n_in,
                              void* d_out, int out_size) {
    const float* x = (const float*)d_in[0];
    const float* inW[2]  = {(const float*)d_in[1],  (const float*)d_in[11]};
    const float* inb[2]  = {(const float*)d_in[2],  (const float*)d_in[12]};
    const float* cw[2]   = {(const float*)d_in[3],  (const float*)d_in[13]};
    const float* cb[2]   = {(const float*)d_in[4],  (const float*)d_in[14]};
    const float* xpW[2]  = {(const float*)d_in[5],  (const float*)d_in[15]};
    const float* xpb[2]  = {(const float*)d_in[6],  (const float*)d_in[16]};
    const float* dtW[2]  = {(const float*)d_in[7],  (const float*)d_in[17]};
    const float* dtb[2]  = {(const float*)d_in[8],  (const float*)d_in[18]};
    const float* outW[2] = {(const float*)d_in[9],  (const float*)d_in[19]};
    const float* outb[2] = {(const float*)d_in[10], (const float*)d_in[20]};
    const float* A_log   = (const float*)d_in[21];
    const float* Dp      = (const float*)d_in[22];
    const float* fuW     = (const float*)d_in[23];
    const float* fub     = (const float*)d_in[24];
    float* out = (float*)d_out;

    cudaFuncSetAttribute(k_mma_gemm<0,0,128>, cudaFuncAttributeMaxDynamicSharedMemorySize, SMEM128);
    cudaFuncSetAttribute(k_mma_gemm<0,1,128>, cudaFuncAttributeMaxDynamicSharedMemorySize, SMEM128);
    cudaFuncSetAttribute(k_mma_gemm<1,0,128>, cudaFuncAttributeMaxDynamicSharedMemorySize, SMEM128);
    cudaFuncSetAttribute(k_mma_gemm<0,2,128>, cudaFuncAttributeMaxDynamicSharedMemorySize, SMEM128);
    cudaFuncSetAttribute(k_mma_gemm<0,0,64>,  cudaFuncAttributeMaxDynamicSharedMemorySize, SMEM64);

    float *xz, *sp, *dtbuf;
    __half *X2h, *sxh, *dh, *yzh, *cth;
    __half *inWt, *xpWt, *dtWt, *outWt, *fuWt;
    cudaGetSymbolAddress((void**)&xz, g_xz);
    cudaGetSymbolAddress((void**)&sp, g_sp);
    cudaGetSymbolAddress((void**)&dtbuf, g_dt);
    cudaGetSymbolAddress((void**)&X2h, g_X2h);
    cudaGetSymbolAddress((void**)&sxh, g_sxh);
    cudaGetSymbolAddress((void**)&dh, g_dh);
    cudaGetSymbolAddress((void**)&yzh, g_yzh);
    cudaGetSymbolAddress((void**)&cth, g_cth);
    cudaGetSymbolAddress((void**)&inWt, g_inW);
    cudaGetSymbolAddress((void**)&xpWt, g_xpW);
    cudaGetSymbolAddress((void**)&dtWt, g_dtW);
    cudaGetSymbolAddress((void**)&outWt, g_outW);
    cudaGetSymbolAddress((void**)&fuWt, g_fuW);

    // 0. fused weight transpose (9 jobs, 1 launch)
    {
        WtJobs jw;
        const float* Ws[9] = {inW[0], inW[1], xpW[0], xpW[1], dtW[0], dtW[1], outW[0], outW[1], fuW};
        __half* Ts[9] = {inWt, inWt + (size_t)DXZ * DM, xpWt, xpWt + (size_t)NSP_PAD * DI,
                         dtWt, dtWt + (size_t)DI * DI, outWt, outWt + (size_t)DM * DI, fuWt};
        int Ks[9]  = {DM, DM, DI, DI, DI, DI, DI, DI, 2 * DM};
        int Ns[9]  = {DXZ, DXZ, NSP, NSP, DI, DI, DM, DM, DM};
        int Nps[9] = {DXZ, DXZ, NSP_PAD, NSP_PAD, DI, DI, DM, DM, DM};
        int ofs = 0;
        jw.ofs[0] = 0;
        for (int j = 0; j < 9; j++) {
            jw.W[j] = Ws[j]; jw.Bt[j] = Ts[j];
            jw.K[j] = Ks[j]; jw.N[j] = Ns[j]; jw.bx[j] = Nps[j] / 32;
            ofs += (Nps[j] / 32) * (Ks[j] / 32);
            jw.ofs[j + 1] = ofs;
        }
        k_wt_all<<<ofs, dim3(32, 8)>>>(jw);
    }

    // 1. prepare inputs
    k_prepare<<<(SL * DM + 255) / 256, 256>>>(x);

    // 2. in-projection: [2048 x 2048], K=512  (BM=128, occ 2)
    {
        TArgs ga = {};
        for (int b = 0; b < 2; b++) {
            ga.Ah[b] = X2h + (size_t)b * SL * DM;
            ga.Bh[b] = inWt + (size_t)b * DXZ * DM;
            ga.bias[b] = inb[b];
            ga.C[b] = xz + (size_t)b * SL * DXZ;
            ga.rev[b] = 0;
        }
        ga.M = SL; ga.N = DXZ; ga.K = DM; ga.ldc = DXZ;
        k_mma_gemm<0,0,128><<<dim3(DXZ / 128, SL / 128, 2), 256, SMEM128>>>(ga);
    }

    // 3. depthwise conv + silu (fp16 out)
    k_conv<<<(2 * SL * DI + 255) / 256, 256>>>(cw[0], cb[0], cw[1], cb[1]);

    // 4. xp-projection: fp32 sp + fused fp16 delta split  (BM=128, occ 2)
    {
        TArgs ga = {};
        for (int b = 0; b < 2; b++) {
            ga.Ah[b] = sxh + (size_t)b * SL * DI;
            ga.Bh[b] = xpWt + (size_t)b * NSP_PAD * DI;
            ga.bias[b] = xpb[b];
            ga.C[b] = sp + (size_t)b * SL * NSP;
            ga.Dh[b] = dh + (size_t)b * SL * DI;
            ga.rev[b] = 0;
        }
        ga.M = SL; ga.N = NSP; ga.K = DI; ga.ldc = NSP; ga.ldd = DI; ga.dlim = DI;
        k_mma_gemm<0,1,128><<<dim3(NSP_PAD / 128, SL / 128, 2), 256, SMEM128>>>(ga);
    }

    // 5. dt-projection + softplus: [2048 x 1024], K=1024  (BM=128, occ 2)
    {
        TArgs ga = {};
        for (int b = 0; b < 2; b++) {
            ga.Ah[b] = dh + (size_t)b * SL * DI;
            ga.Bh[b] = dtWt + (size_t)b * DI * DI;
            ga.bias[b] = dtb[b];
            ga.C[b] = dtbuf + (size_t)b * SL * DI;
            ga.rev[b] = 0;
        }
        ga.M = SL; ga.N = DI; ga.K = DI; ga.ldc = DI;
        k_mma_gemm<1,0,128><<<dim3(DI / 128, SL / 128, 2), 256, SMEM128>>>(ga);
    }

    // 6. chunked selective scan (A, then C with inlined combine)
    k_scanA<<<dim3(DI / 128, NCH, 2), 128>>>(A_log);
    k_scanC<<<dim3(DI / 128, NCH, 2), 128>>>(A_log, Dp);

    // 7. out-projection: fp16 concat only (bwd rows reversed back)  (BM=128, occ 2)
    {
        TArgs ga = {};
        for (int b = 0; b < 2; b++) {
            ga.Ah[b] = yzh + (size_t)b * SL * DI;
            ga.Bh[b] = outWt + (size_t)b * DM * DI;
            ga.bias[b] = outb[b];
            ga.Dh[b] = cth + b * DM;
            ga.rev[b] = (b == 1);
        }
        ga.M = SL; ga.N = DM; ga.K = DI; ga.ldd = 2 * DM;
        k_mma_gemm<0,2,128><<<dim3(DM / 128, SL / 128, 2), 256, SMEM128>>>(ga);
    }

    // 8. fusion: [2048 x 512], K=1024  (BM=64, occ 2 -> 128 CTAs)
    {
        TArgs ga = {};
        ga.Ah[0] = ga.Ah[1] = cth;
        ga.Bh[0] = ga.Bh[1] = fuWt;
        ga.bias[0] = ga.bias[1] = fub;
        ga.C[0] = ga.C[1] = out;
        ga.rev[0] = ga.rev[1] = 0;
        ga.M = SL; ga.N = DM; ga.K = 2 * DM; ga.ldc = DM;
        k_mma_gemm<0,0,64><<<dim3(DM / 128, SL / 64, 1), 256, SMEM64>>>(ga);
    }
}